// round 15
// baseline (speedup 1.0000x reference)
#include <cuda_runtime.h>
#include <cstdint>

// Haar (db1) 2-D DWT on (B=16, C=3, H=1024, W=1024) fp32.
// Output: concatenated planes [cA | cH | cV | cD], each (16,3,512,512).
//
// R15: R2/R13 config (2 rows x 8 cols per thread, __stcs float4 stores,
// 32 regs, 256-thr CTAs) with the loads widened to Blackwell 256-bit
// ld.global.v8.f32 (2 LDG.256 instead of 4 LDG.128 per thread): halves
// LSU dispatch slots + L1tex wavefront-queue entries per byte. DRAM-side
// expectation unchanged (ceiling is path-independent); issue-side only.

static constexpr int Bc    = 16 * 3;        // images
static constexpr int H     = 1024;
static constexpr int W     = 1024;
static constexpr int H2    = H / 2;         // 512
static constexpr int W2    = W / 2;         // 512
static constexpr int W8    = W / 8;         // 8-col tiles per row = 128
static constexpr int PLANE = Bc * H2 * W2;  // elements per output plane

// 256-bit global load: 8 consecutive floats (sm_100+/PTX 8.7+).
__device__ __forceinline__ void ldg256(const float* p,
                                       float4& lo, float4& hi) {
    asm volatile(
        "ld.global.v8.f32 {%0,%1,%2,%3,%4,%5,%6,%7}, [%8];"
        : "=f"(lo.x), "=f"(lo.y), "=f"(lo.z), "=f"(lo.w),
          "=f"(hi.x), "=f"(hi.y), "=f"(hi.z), "=f"(hi.w)
        : "l"(p));
}

__global__ __launch_bounds__(256, 8)
void haar_dwt_kernel(const float* __restrict__ x, float* __restrict__ out) {
    int t = blockIdx.x * blockDim.x + threadIdx.x;
    // t in [0, Bc*H2*W8)
    int j  = t & (W8 - 1);          // 8-col tile index
    int r  = t >> 7;                // / W8
    int i  = r & (H2 - 1);          // output row
    int bc = r >> 9;                // / H2

    const float* row0 = x + (size_t)bc * H * W + (size_t)(2 * i) * W + 8 * j;
    const float* row1 = row0 + W;

    // 2 front-batched 256-bit loads (32 B each, 8-float aligned: 8j*4 % 32 == 0)
    float4 a0, a1, b0, b1;
    ldg256(row0, a0, a1);           // row 2i,   cols 8j..8j+7
    ldg256(row1, b0, b1);           // row 2i+1, cols 8j..8j+7

    float s0 = a0.x + a0.y, d0 = a0.x - a0.y;
    float s1 = b0.x + b0.y, d1 = b0.x - b0.y;
    float s2 = a0.z + a0.w, d2 = a0.z - a0.w;
    float s3 = b0.z + b0.w, d3 = b0.z - b0.w;
    float s4 = a1.x + a1.y, d4 = a1.x - a1.y;
    float s5 = b1.x + b1.y, d5 = b1.x - b1.y;
    float s6 = a1.z + a1.w, d6 = a1.z - a1.w;
    float s7 = b1.z + b1.w, d7 = b1.z - b1.w;

    float4 cA = make_float4((s0 + s1) * 0.5f, (s2 + s3) * 0.5f,
                            (s4 + s5) * 0.5f, (s6 + s7) * 0.5f);
    float4 cH = make_float4((s0 - s1) * 0.5f, (s2 - s3) * 0.5f,
                            (s4 - s5) * 0.5f, (s6 - s7) * 0.5f);
    float4 cV = make_float4((d0 + d1) * 0.5f, (d2 + d3) * 0.5f,
                            (d4 + d5) * 0.5f, (d6 + d7) * 0.5f);
    float4 cD = make_float4((d0 - d1) * 0.5f, (d2 - d3) * 0.5f,
                            (d4 - d5) * 0.5f, (d6 - d7) * 0.5f);

    size_t o = (size_t)bc * H2 * W2 + (size_t)i * W2 + 4 * j;  // 16B aligned
    __stcs(reinterpret_cast<float4*>(out + o),                      cA);
    __stcs(reinterpret_cast<float4*>(out + PLANE + o),              cH);
    __stcs(reinterpret_cast<float4*>(out + 2 * (size_t)PLANE + o),  cV);
    __stcs(reinterpret_cast<float4*>(out + 3 * (size_t)PLANE + o),  cD);
}

extern "C" void kernel_launch(void* const* d_in, const int* in_sizes, int n_in,
                              void* d_out, int out_size) {
    const float* x  = (const float*)d_in[0];
    float* out      = (float*)d_out;

    int total_threads = Bc * H2 * W8;          // 3,145,728
    int block = 256;
    int grid  = total_threads / block;         // 12288
    haar_dwt_kernel<<<grid, block>>>(x, out);
}

// round 16
// speedup vs baseline: 1.0167x; 1.0167x over previous
#include <cuda_runtime.h>
#include <cstdint>

// Haar (db1) 2-D DWT on (B=16, C=3, H=1024, W=1024) fp32.
// Output: concatenated planes [cA | cH | cV | cD], each (16,3,512,512).
//
// FINAL — locked at the machine ceiling (R2/R13 config, best of 9 variants):
// one thread = 4 adjacent 2x2 blocks (2 input rows x 8 cols).
// 4 front-batched __ldcs float4 loads (MLP=4), one __stcs float4 store
// per output plane. 32 regs, 256-thr CTAs, 12288 CTAs.
//
// Evidence trail: 6.13-6.28 TB/s across ALL well-formed variants —
// store width (64/128-bit), store policy (stcs/default), read hints,
// tile depth (2x8 vs 4x8), CTA size (128/256), persistent grid-stride,
// and 256-bit LDG all null or negative. Binding resource: DRAM bus at
// ~78% of 8 TB/s spec for a balanced read+write stream; traffic (402 MB
// through L2, ~350 MB DRAM after L2 write absorption) is irreducible
// (zero reuse, fully coalesced, layout fixed by reference). Occupancy /
// issue never binding (occ up + DRAM down in the persistent variant).

static constexpr int Bc    = 16 * 3;        // images
static constexpr int H     = 1024;
static constexpr int W     = 1024;
static constexpr int H2    = H / 2;         // 512
static constexpr int W2    = W / 2;         // 512
static constexpr int W8    = W / 8;         // 8-col tiles per row = 128
static constexpr int PLANE = Bc * H2 * W2;  // elements per output plane

__global__ __launch_bounds__(256, 8)
void haar_dwt_kernel(const float* __restrict__ x, float* __restrict__ out) {
    int t = blockIdx.x * blockDim.x + threadIdx.x;
    // t in [0, Bc*H2*W8)
    int j  = t & (W8 - 1);          // 8-col tile index
    int r  = t >> 7;                // / W8
    int i  = r & (H2 - 1);          // output row
    int bc = r >> 9;                // / H2

    const float4* row0 = reinterpret_cast<const float4*>(
        x + (size_t)bc * H * W + (size_t)(2 * i) * W) + 2 * j;
    const float4* row1 = row0 + (W / 4);

    // front-batch all 4 loads (MLP=4), streaming/evict-first (no reuse)
    float4 a0 = __ldcs(row0);       // row 2i,   cols 8j..8j+3
    float4 a1 = __ldcs(row0 + 1);   // row 2i,   cols 8j+4..8j+7
    float4 b0 = __ldcs(row1);       // row 2i+1, cols 8j..8j+3
    float4 b1 = __ldcs(row1 + 1);   // row 2i+1, cols 8j+4..8j+7

    float s0 = a0.x + a0.y, d0 = a0.x - a0.y;
    float s1 = b0.x + b0.y, d1 = b0.x - b0.y;
    float s2 = a0.z + a0.w, d2 = a0.z - a0.w;
    float s3 = b0.z + b0.w, d3 = b0.z - b0.w;
    float s4 = a1.x + a1.y, d4 = a1.x - a1.y;
    float s5 = b1.x + b1.y, d5 = b1.x - b1.y;
    float s6 = a1.z + a1.w, d6 = a1.z - a1.w;
    float s7 = b1.z + b1.w, d7 = b1.z - b1.w;

    float4 cA = make_float4((s0 + s1) * 0.5f, (s2 + s3) * 0.5f,
                            (s4 + s5) * 0.5f, (s6 + s7) * 0.5f);
    float4 cH = make_float4((s0 - s1) * 0.5f, (s2 - s3) * 0.5f,
                            (s4 - s5) * 0.5f, (s6 - s7) * 0.5f);
    float4 cV = make_float4((d0 + d1) * 0.5f, (d2 + d3) * 0.5f,
                            (d4 + d5) * 0.5f, (d6 + d7) * 0.5f);
    float4 cD = make_float4((d0 - d1) * 0.5f, (d2 - d3) * 0.5f,
                            (d4 - d5) * 0.5f, (d6 - d7) * 0.5f);

    size_t o = (size_t)bc * H2 * W2 + (size_t)i * W2 + 4 * j;  // 16B aligned
    __stcs(reinterpret_cast<float4*>(out + o),                      cA);
    __stcs(reinterpret_cast<float4*>(out + PLANE + o),              cH);
    __stcs(reinterpret_cast<float4*>(out + 2 * (size_t)PLANE + o),  cV);
    __stcs(reinterpret_cast<float4*>(out + 3 * (size_t)PLANE + o),  cD);
}

extern "C" void kernel_launch(void* const* d_in, const int* in_sizes, int n_in,
                              void* d_out, int out_size) {
    const float* x  = (const float*)d_in[0];
    float* out      = (float*)d_out;

    int total_threads = Bc * H2 * W8;          // 3,145,728
    int block = 256;
    int grid  = total_threads / block;         // 12288
    haar_dwt_kernel<<<grid, block>>>(x, out);
}

// round 17
// speedup vs baseline: 1.0367x; 1.0196x over previous
#include <cuda_runtime.h>
#include <cstdint>

// Haar (db1) 2-D DWT on (B=16, C=3, H=1024, W=1024) fp32.
// Output: concatenated planes [cA | cH | cV | cD], each (16,3,512,512).
//
// FINAL — locked at the machine ceiling (best of 9 variants, confirmed
// across 4 runs: harness 63.2/63.4/63.5/63.2 us, HBM 6.21-6.28 TB/s):
// one thread = 4 adjacent 2x2 blocks (2 input rows x 8 cols).
// 4 front-batched __ldcs float4 loads (MLP=4), one __stcs float4 store
// per output plane. 32 regs, 256-thr CTAs, 12288 CTAs.
//
// Evidence trail: store width (64/128-bit), store policy (stcs/default),
// read hints, tile depth (2x8 vs 4x8), CTA size (128/256), persistent
// grid-stride, and 256-bit LDG all null or negative — every well-formed
// variant pins at 6.13-6.28 TB/s. Binding resource: DRAM bus at ~78% of
// 8 TB/s spec for a balanced 1:1 read/write stream; traffic (402 MB via
// L2, ~350 MB DRAM after L2 write absorption) is irreducible (zero reuse,
// fully coalesced, layout fixed by reference). Occupancy/issue never
// binding (occ up + DRAM down in the persistent variant falsified the
// demand-starvation model).

static constexpr int Bc    = 16 * 3;        // images
static constexpr int H     = 1024;
static constexpr int W     = 1024;
static constexpr int H2    = H / 2;         // 512
static constexpr int W2    = W / 2;         // 512
static constexpr int W8    = W / 8;         // 8-col tiles per row = 128
static constexpr int PLANE = Bc * H2 * W2;  // elements per output plane

__global__ __launch_bounds__(256, 8)
void haar_dwt_kernel(const float* __restrict__ x, float* __restrict__ out) {
    int t = blockIdx.x * blockDim.x + threadIdx.x;
    // t in [0, Bc*H2*W8)
    int j  = t & (W8 - 1);          // 8-col tile index
    int r  = t >> 7;                // / W8
    int i  = r & (H2 - 1);          // output row
    int bc = r >> 9;                // / H2

    const float4* row0 = reinterpret_cast<const float4*>(
        x + (size_t)bc * H * W + (size_t)(2 * i) * W) + 2 * j;
    const float4* row1 = row0 + (W / 4);

    // front-batch all 4 loads (MLP=4), streaming/evict-first (no reuse)
    float4 a0 = __ldcs(row0);       // row 2i,   cols 8j..8j+3
    float4 a1 = __ldcs(row0 + 1);   // row 2i,   cols 8j+4..8j+7
    float4 b0 = __ldcs(row1);       // row 2i+1, cols 8j..8j+3
    float4 b1 = __ldcs(row1 + 1);   // row 2i+1, cols 8j+4..8j+7

    float s0 = a0.x + a0.y, d0 = a0.x - a0.y;
    float s1 = b0.x + b0.y, d1 = b0.x - b0.y;
    float s2 = a0.z + a0.w, d2 = a0.z - a0.w;
    float s3 = b0.z + b0.w, d3 = b0.z - b0.w;
    float s4 = a1.x + a1.y, d4 = a1.x - a1.y;
    float s5 = b1.x + b1.y, d5 = b1.x - b1.y;
    float s6 = a1.z + a1.w, d6 = a1.z - a1.w;
    float s7 = b1.z + b1.w, d7 = b1.z - b1.w;

    float4 cA = make_float4((s0 + s1) * 0.5f, (s2 + s3) * 0.5f,
                            (s4 + s5) * 0.5f, (s6 + s7) * 0.5f);
    float4 cH = make_float4((s0 - s1) * 0.5f, (s2 - s3) * 0.5f,
                            (s4 - s5) * 0.5f, (s6 - s7) * 0.5f);
    float4 cV = make_float4((d0 + d1) * 0.5f, (d2 + d3) * 0.5f,
                            (d4 + d5) * 0.5f, (d6 + d7) * 0.5f);
    float4 cD = make_float4((d0 - d1) * 0.5f, (d2 - d3) * 0.5f,
                            (d4 - d5) * 0.5f, (d6 - d7) * 0.5f);

    size_t o = (size_t)bc * H2 * W2 + (size_t)i * W2 + 4 * j;  // 16B aligned
    __stcs(reinterpret_cast<float4*>(out + o),                      cA);
    __stcs(reinterpret_cast<float4*>(out + PLANE + o),              cH);
    __stcs(reinterpret_cast<float4*>(out + 2 * (size_t)PLANE + o),  cV);
    __stcs(reinterpret_cast<float4*>(out + 3 * (size_t)PLANE + o),  cD);
}

extern "C" void kernel_launch(void* const* d_in, const int* in_sizes, int n_in,
                              void* d_out, int out_size) {
    const float* x  = (const float*)d_in[0];
    float* out      = (float*)d_out;

    int total_threads = Bc * H2 * W8;          // 3,145,728
    int block = 256;
    int grid  = total_threads / block;         // 12288
    haar_dwt_kernel<<<grid, block>>>(x, out);
}